// round 6
// baseline (speedup 1.0000x reference)
#include <cuda_runtime.h>
#include <cstdint>

#define N_IN    6
#define N_MF    4
#define N_RULES 4096
#define BATCH   4096
#define BT      32
#define NWARPS  32
#define NTHREADS 1024
#define NBLOCKS (BATCH / BT)     // 128

// smem (floats): Cs 128KB + Qpsh 8KB + msh + xrsh + accsh 28KB ~= 166KB
#define CS_F   (2048 * 16)
#define QP_F   (32 * BT * 2)
#define MSH_F  (12 * BT)
#define XR_F   (7 * BT)
#define ACC_F  (NWARPS * 7 * BT)
#define SMEM_BYTES ((CS_F + QP_F + MSH_F + XR_F + ACC_F) * 4)

__device__ __forceinline__ unsigned long long pk2(float lo, float hi) {
    unsigned long long r;
    asm("mov.b64 %0, {%1, %2};" : "=l"(r) : "f"(lo), "f"(hi));
    return r;
}
__device__ __forceinline__ unsigned long long mul2(unsigned long long a, unsigned long long b) {
    unsigned long long r;
    asm("mul.rn.f32x2 %0, %1, %2;" : "=l"(r) : "l"(a), "l"(b));
    return r;
}
__device__ __forceinline__ void fma2(unsigned long long& acc, unsigned long long a, unsigned long long b) {
    asm("fma.rn.f32x2 %0, %1, %2, %0;" : "+l"(acc) : "l"(a), "l"(b));
}

__global__ void __launch_bounds__(NTHREADS, 1) anfis_fused_kernel(
    const float* __restrict__ x, const float* __restrict__ a,
    const float* __restrict__ b, const float* __restrict__ c,
    const float* __restrict__ coeff, float* __restrict__ out)
{
    extern __shared__ float smem[];
    float* Cs    = smem;                 // pair p: [j0r0,j0r1,...,j6r0,j6r1,pad,pad]
    float* Qpsh  = Cs + CS_F;            // u64 Q-pairs, [m][lane]
    float* msh   = Qpsh + QP_F;          // memberships inputs 0..2: [i*4+k][lane]
    float* xrsh  = msh + MSH_F;          // xi[0..5], rden : [j][lane]
    float* accsh = xrsh + XR_F;          // [warp][j][lane]

    const int tid  = threadIdx.x;
    const int lane = tid & 31;
    const int wid  = tid >> 5;
    const int b0   = blockIdx.x * BT;

    // ---- Stage coeff (coalesced LDG, pair-interleaved STS), all 1024 threads ----
    #pragma unroll
    for (int it = 0; it < (N_RULES * 7) / NTHREADS; it++) {
        int idx = it * NTHREADS + tid;
        float v = __ldg(&coeff[idx]);
        int r = idx / 7;
        int j = idx - r * 7;
        Cs[(r >> 1) * 16 + j * 2 + (r & 1)] = v;
    }

    // ---- Phase 1: only warps 0 & 1 compute memberships (keeps reg pressure low) ----
    if (wid < 2) {
        const int bb = b0 + lane;
        float xi[N_IN];
        float mm[N_IN][N_MF];
        float den = 1.0f;
        #pragma unroll
        for (int i = 0; i < N_IN; i++) {
            xi[i] = __ldg(&x[bb * N_IN + i]);
            float s = 0.0f;
            #pragma unroll
            for (int k = 0; k < N_MF; k++) {
                float av = __ldg(&a[i * N_MF + k]);
                float bv = __ldg(&b[i * N_MF + k]);
                float cv = __ldg(&c[i * N_MF + k]);
                float d  = (xi[i] - cv) / av;
                float d2 = d * d;
                float db = (bv == 2.0f) ? (d2 * d2) : __powf(d2, bv);
                float mv = 1.0f / (1.0f + db);
                mm[i][k] = mv;
                s += mv;
            }
            den *= s;
        }
        if (wid == 0) {
            #pragma unroll
            for (int i = 0; i < 3; i++)
                #pragma unroll
                for (int k = 0; k < N_MF; k++)
                    msh[(i * N_MF + k) * BT + lane] = mm[i][k];
            #pragma unroll
            for (int j = 0; j < 6; j++)
                xrsh[j * BT + lane] = xi[j];
            xrsh[6 * BT + lane] = 1.0f / fmaxf(den, 1e-12f);
        } else {
            // Q pairs: Qp[m] = (Q[2m], Q[2m+1]), lane-linear u64 layout
            unsigned long long m5p0 = pk2(mm[5][0], mm[5][1]);
            unsigned long long m5p1 = pk2(mm[5][2], mm[5][3]);
            unsigned long long* Qq = reinterpret_cast<unsigned long long*>(Qpsh);
            #pragma unroll
            for (int ab = 0; ab < 16; ab++) {
                float tt = mm[3][ab >> 2] * mm[4][ab & 3];
                unsigned long long ttp = pk2(tt, tt);
                Qq[(2 * ab) * BT + lane]     = mul2(ttp, m5p0);
                Qq[(2 * ab + 1) * BT + lane] = mul2(ttp, m5p1);
            }
        }
    }
    __syncthreads();

    // ---- Phase 2: each warp covers rhi = {2w, 2w+1} (64 rules each) ----
    unsigned long long acc[7];
    #pragma unroll
    for (int j = 0; j < 7; j++) acc[j] = 0ull;

    const unsigned long long* Qq = reinterpret_cast<const unsigned long long*>(Qpsh);

    #pragma unroll
    for (int hh = 0; hh < 2; hh++) {
        const int rhi = 2 * wid + hh;
        const float Pv = msh[(0 * N_MF + ((rhi >> 4) & 3)) * BT + lane]
                       * msh[(1 * N_MF + ((rhi >> 2) & 3)) * BT + lane]
                       * msh[(2 * N_MF + (rhi & 3)) * BT + lane];
        const unsigned long long PP = pk2(Pv, Pv);
        const ulonglong2* __restrict__ Cp =
            reinterpret_cast<const ulonglong2*>(Cs + (size_t)rhi * 512);
        #pragma unroll
        for (int m = 0; m < 32; m++) {
            ulonglong2 v0 = Cp[4 * m + 0];   // c(j0,j1)
            ulonglong2 v1 = Cp[4 * m + 1];   // c(j2,j3)
            ulonglong2 v2 = Cp[4 * m + 2];   // c(j4,j5)
            unsigned long long c6 = reinterpret_cast<const unsigned long long*>(Cp)[8 * m + 6];
            unsigned long long q  = Qq[m * BT + lane];
            unsigned long long ww = mul2(PP, q);
            fma2(acc[0], ww, v0.x);
            fma2(acc[1], ww, v0.y);
            fma2(acc[2], ww, v1.x);
            fma2(acc[3], ww, v1.y);
            fma2(acc[4], ww, v2.x);
            fma2(acc[5], ww, v2.y);
            fma2(acc[6], ww, c6);
        }
    }

    // fold even/odd rule halves, stash per-warp partials
    #pragma unroll
    for (int j = 0; j < 7; j++) {
        float e, o;
        asm("mov.b64 {%0, %1}, %2;" : "=f"(e), "=f"(o) : "l"(acc[j]));
        accsh[(wid * 7 + j) * BT + lane] = e + o;
    }
    __syncthreads();

    // ---- Phase 3 (warp 0): reduce 32 warps, TSK dot, normalize ----
    if (wid == 0) {
        float num = 0.0f;
        #pragma unroll
        for (int j = 0; j < 7; j++) {
            float D = 0.0f;
            #pragma unroll
            for (int w = 0; w < NWARPS; w++)
                D += accsh[(w * 7 + j) * BT + lane];
            float xp = (j < 6) ? xrsh[j * BT + lane] : 1.0f;
            num = fmaf(xp, D, num);
        }
        out[b0 + lane] = num * xrsh[6 * BT + lane];
    }
}

extern "C" void kernel_launch(void* const* d_in, const int* in_sizes, int n_in,
                              void* d_out, int out_size) {
    const float* x     = (const float*)d_in[0];
    const float* a     = (const float*)d_in[1];
    const float* b     = (const float*)d_in[2];
    const float* c     = (const float*)d_in[3];
    const float* coeff = (const float*)d_in[4];
    // d_in[5] = mf_indices: full itertools.product enumeration; digit decode is analytic.
    float* out = (float*)d_out;

    static bool attr_set = false;
    if (!attr_set) {
        cudaFuncSetAttribute(anfis_fused_kernel,
                             cudaFuncAttributeMaxDynamicSharedMemorySize, SMEM_BYTES);
        attr_set = true;
    }
    anfis_fused_kernel<<<NBLOCKS, NTHREADS, SMEM_BYTES>>>(x, a, b, c, coeff, out);
}

// round 8
// speedup vs baseline: 1.3088x; 1.3088x over previous
#include <cuda_runtime.h>
#include <cuda_bf16.h>
#include <cstdint>

#define BATCH    4096
#define MTILE    32
#define NBLOCKS  (BATCH / MTILE)   // 128
#define NTHREADS 256               // 8 warps
#define NCOLS    448               // 64 h * 7 j
#define KD       64

// smem byte offsets. A/B: [row][64 bf16] rows of 128B, XOR-16B swizzle.
#define OFF_AH   0
#define OFF_AL   4096
#define OFF_BH   8192
#define OFF_BL   (8192 + 57344)            // 65536
#define OFF_P    (OFF_BL + 57344)          // 122880  (64 x stride33 f32)
#define OFF_XP   (OFF_P + 64 * 33 * 4)     // 131328  (7 x stride33 f32)
#define OFF_RD   (OFF_XP + 7 * 33 * 4)     // 132252
#define OFF_RED  (OFF_RD + 128)            // 132380  (8 warps x 32 rows f32)
#define SMEM_BYTES (OFF_RED + 8 * 32 * 4 + 16)

static __device__ __forceinline__ uint32_t packbf2(__nv_bfloat16 lo, __nv_bfloat16 hi) {
    __nv_bfloat162 t(lo, hi);
    return *reinterpret_cast<uint32_t*>(&t);
}
static __device__ __forceinline__ void bsplit(float v, __nv_bfloat16& h, __nv_bfloat16& l) {
    h = __float2bfloat16(v);
    l = __float2bfloat16(v - __bfloat162float(h));
}
static __device__ __forceinline__ void mma16816(float* d, const uint32_t* a,
                                                uint32_t b0, uint32_t b1) {
    asm("mma.sync.aligned.m16n8k16.row.col.f32.bf16.bf16.f32 "
        "{%0,%1,%2,%3}, {%4,%5,%6,%7}, {%8,%9}, {%0,%1,%2,%3};"
        : "+f"(d[0]), "+f"(d[1]), "+f"(d[2]), "+f"(d[3])
        : "r"(a[0]), "r"(a[1]), "r"(a[2]), "r"(a[3]), "r"(b0), "r"(b1));
}

__global__ void __launch_bounds__(NTHREADS, 1) anfis_hmma_kernel(
    const float* __restrict__ x, const float* __restrict__ a,
    const float* __restrict__ b, const float* __restrict__ c,
    const float* __restrict__ coeff, float* __restrict__ out)
{
    extern __shared__ char smem[];
    const int tid  = threadIdx.x;
    const int lane = tid & 31;
    const int wid  = tid >> 5;
    const int b0   = blockIdx.x * MTILE;

    // ---- Stage B: coeff -> bf16 hi/lo at row n=(h*7+j), col k=l, swizzled ----
    for (int i = tid; i < 4096 * 7; i += NTHREADS) {
        float v = __ldg(&coeff[i]);
        int r = i / 7, j = i - r * 7;
        int n = (r >> 6) * 7 + j;
        int k = r & 63;
        __nv_bfloat16 vh, vl;
        bsplit(v, vh, vl);
        uint32_t cb = (uint32_t)(k * 2) ^ (uint32_t)((n & 7) << 4);
        *reinterpret_cast<__nv_bfloat16*>(smem + OFF_BH + n * 128 + cb) = vh;
        *reinterpret_cast<__nv_bfloat16*>(smem + OFF_BL + n * 128 + cb) = vl;
    }

    // ---- Memberships: warp 0 -> P/xp/rden tables, warp 1 -> A (Q) tiles ----
    if (wid < 2) {
        const int bl = lane;
        const int bb = b0 + bl;
        float xi[6], mm[6][4];
        float den = 1.0f;
        #pragma unroll
        for (int i = 0; i < 6; i++) {
            xi[i] = __ldg(&x[bb * 6 + i]);
            float s = 0.0f;
            #pragma unroll
            for (int k = 0; k < 4; k++) {
                float av = __ldg(&a[i * 4 + k]);
                float bv = __ldg(&b[i * 4 + k]);
                float cv = __ldg(&c[i * 4 + k]);
                float d  = (xi[i] - cv) / av;
                float d2 = d * d;
                float db = (bv == 2.0f) ? (d2 * d2) : __powf(d2, bv);
                float mv = 1.0f / (1.0f + db);
                mm[i][k] = mv;
                s += mv;
            }
            den *= s;
        }
        if (wid == 0) {
            float* Ps = reinterpret_cast<float*>(smem + OFF_P);
            float* Xs = reinterpret_cast<float*>(smem + OFF_XP);
            float* Rd = reinterpret_cast<float*>(smem + OFF_RD);
            #pragma unroll
            for (int j = 0; j < 6; j++) Xs[j * 33 + bl] = xi[j];
            Xs[6 * 33 + bl] = 1.0f;
            Rd[bl] = 1.0f / fmaxf(den, 1e-12f);
            float m01[16];
            #pragma unroll
            for (int u = 0; u < 4; u++)
                #pragma unroll
                for (int v = 0; v < 4; v++) m01[u * 4 + v] = mm[0][u] * mm[1][v];
            #pragma unroll
            for (int h = 0; h < 64; h++)
                Ps[h * 33 + bl] = m01[h >> 2] * mm[2][h & 3];
        } else {
            float m34[16];
            #pragma unroll
            for (int u = 0; u < 4; u++)
                #pragma unroll
                for (int v = 0; v < 4; v++) m34[u * 4 + v] = mm[3][u] * mm[4][v];
            #pragma unroll
            for (int l = 0; l < 64; l += 2) {
                float q0 = m34[l >> 2] * mm[5][l & 3];
                float q1 = m34[(l + 1) >> 2] * mm[5][(l + 1) & 3];
                __nv_bfloat16 h0, l0, h1, l1;
                bsplit(q0, h0, l0);
                bsplit(q1, h1, l1);
                uint32_t cb = (uint32_t)(l * 2) ^ (uint32_t)((bl & 7) << 4);
                *reinterpret_cast<uint32_t*>(smem + OFF_AH + bl * 128 + cb) = packbf2(h0, h1);
                *reinterpret_cast<uint32_t*>(smem + OFF_AL + bl * 128 + cb) = packbf2(l0, l1);
            }
        }
    }
    __syncthreads();

    // ---- HMMA mainloop: warp = 56-col chunk; 2 mtiles x 7 ntiles x 3 terms ----
    float acc[2][7][4];
    #pragma unroll
    for (int mt = 0; mt < 2; mt++)
        #pragma unroll
        for (int nt = 0; nt < 7; nt++)
            #pragma unroll
            for (int e = 0; e < 4; e++) acc[mt][nt][e] = 0.0f;

    const int r  = lane >> 2;
    const int c4 = (lane & 3) * 4;
    const uint32_t rsw = (uint32_t)(r << 4);

    #pragma unroll
    for (int ks = 0; ks < 4; ks++) {
        const uint32_t cb0 = (uint32_t)(ks * 32 + c4) ^ rsw;
        const uint32_t cb1 = (uint32_t)(ks * 32 + c4 + 16) ^ rsw;
        uint32_t ah[2][4], al[2][4];
        #pragma unroll
        for (int mt = 0; mt < 2; mt++) {
            const int row = mt * 16 + r;
            ah[mt][0] = *reinterpret_cast<const uint32_t*>(smem + OFF_AH + row * 128 + cb0);
            ah[mt][1] = *reinterpret_cast<const uint32_t*>(smem + OFF_AH + (row + 8) * 128 + cb0);
            ah[mt][2] = *reinterpret_cast<const uint32_t*>(smem + OFF_AH + row * 128 + cb1);
            ah[mt][3] = *reinterpret_cast<const uint32_t*>(smem + OFF_AH + (row + 8) * 128 + cb1);
            al[mt][0] = *reinterpret_cast<const uint32_t*>(smem + OFF_AL + row * 128 + cb0);
            al[mt][1] = *reinterpret_cast<const uint32_t*>(smem + OFF_AL + (row + 8) * 128 + cb0);
            al[mt][2] = *reinterpret_cast<const uint32_t*>(smem + OFF_AL + row * 128 + cb1);
            al[mt][3] = *reinterpret_cast<const uint32_t*>(smem + OFF_AL + (row + 8) * 128 + cb1);
        }
        #pragma unroll
        for (int nt = 0; nt < 7; nt++) {
            const int n = wid * 56 + nt * 8 + r;      // n & 7 == r
            uint32_t bh0 = *reinterpret_cast<const uint32_t*>(smem + OFF_BH + n * 128 + cb0);
            uint32_t bh1 = *reinterpret_cast<const uint32_t*>(smem + OFF_BH + n * 128 + cb1);
            uint32_t bl0 = *reinterpret_cast<const uint32_t*>(smem + OFF_BL + n * 128 + cb0);
            uint32_t bl1 = *reinterpret_cast<const uint32_t*>(smem + OFF_BL + n * 128 + cb1);
            #pragma unroll
            for (int mt = 0; mt < 2; mt++) {
                mma16816(acc[mt][nt], ah[mt], bh0, bh1);   // hi*hi
                mma16816(acc[mt][nt], ah[mt], bl0, bl1);   // hi*lo
                mma16816(acc[mt][nt], al[mt], bh0, bh1);   // lo*hi
            }
        }
    }

    // ---- Epilogue: fold P * x_plus into fragments, reduce to rows ----
    {
        const float* Ps = reinterpret_cast<const float*>(smem + OFF_P);
        const float* Xs = reinterpret_cast<const float*>(smem + OFF_XP);
        float rsum[4] = {0.f, 0.f, 0.f, 0.f};
        #pragma unroll
        for (int mt = 0; mt < 2; mt++)
            #pragma unroll
            for (int nt = 0; nt < 7; nt++)
                #pragma unroll
                for (int e = 0; e < 4; e++) {
                    const int row = mt * 16 + r + (e >> 1) * 8;
                    const int u   = nt * 8 + 2 * (lane & 3) + (e & 1);
                    const int h   = u / 7;
                    const int j   = u - h * 7;
                    float pv = Ps[(wid * 8 + h) * 33 + row];
                    float xv = Xs[j * 33 + row];
                    rsum[mt * 2 + (e >> 1)] =
                        fmaf(pv * xv, acc[mt][nt][e], rsum[mt * 2 + (e >> 1)]);
                }
        #pragma unroll
        for (int i = 0; i < 4; i++) {
            rsum[i] += __shfl_xor_sync(0xFFFFFFFFu, rsum[i], 1);
            rsum[i] += __shfl_xor_sync(0xFFFFFFFFu, rsum[i], 2);
        }
        if ((lane & 3) == 0) {
            float* red = reinterpret_cast<float*>(smem + OFF_RED);
            #pragma unroll
            for (int i = 0; i < 4; i++)
                red[wid * 32 + r + 8 * i] = rsum[i];
        }
    }
    __syncthreads();

    // ---- Final: sum 8 warp chunks, normalize, store ----
    if (tid < MTILE) {
        const float* red = reinterpret_cast<const float*>(smem + OFF_RED);
        const float* Rd  = reinterpret_cast<const float*>(smem + OFF_RD);
        float num = 0.0f;
        #pragma unroll
        for (int w = 0; w < 8; w++) num += red[w * 32 + tid];
        out[b0 + tid] = num * Rd[tid];
    }
}

extern "C" void kernel_launch(void* const* d_in, const int* in_sizes, int n_in,
                              void* d_out, int out_size) {
    const float* x     = (const float*)d_in[0];
    const float* a     = (const float*)d_in[1];
    const float* b     = (const float*)d_in[2];
    const float* c     = (const float*)d_in[3];
    const float* coeff = (const float*)d_in[4];
    // d_in[5] = mf_indices: full itertools.product enumeration; base-4 digit
    // decode is analytic, index tensor unused.
    float* out = (float*)d_out;

    static bool attr_set = false;
    if (!attr_set) {
        cudaFuncSetAttribute(anfis_hmma_kernel,
                             cudaFuncAttributeMaxDynamicSharedMemorySize, SMEM_BYTES);
        attr_set = true;
    }
    anfis_hmma_kernel<<<NBLOCKS, NTHREADS, SMEM_BYTES>>>(x, a, b, c, coeff, out);
}

// round 9
// speedup vs baseline: 1.9600x; 1.4975x over previous
#include <cuda_runtime.h>
#include <cuda_bf16.h>
#include <cstdint>

#define BATCH    4096
#define MTILE    32
#define NBLOCKS  (BATCH / MTILE)   // 128
#define NTHREADS 256               // 8 warps
#define NCOLS    448               // 64 h * 7 j
#define B_BYTES  (NCOLS * 128)     // 57344 per split term

// Pre-converted B tiles (bf16 hi/lo), already in swizzled [n][128B] layout
__device__ __align__(16) unsigned char g_bh[B_BYTES];
__device__ __align__(16) unsigned char g_bl[B_BYTES];

// smem byte offsets
#define OFF_AH   0
#define OFF_AL   4096
#define OFF_BH   8192
#define OFF_BL   (OFF_BH + B_BYTES)        // 65536
#define OFF_P    (OFF_BL + B_BYTES)        // 122880  (64 x stride33 f32)
#define OFF_XP   (OFF_P + 64 * 33 * 4)     // 131328  (7 x stride33 f32)
#define OFF_RD   (OFF_XP + 7 * 33 * 4)
#define OFF_RED  (OFF_RD + 128)            // 8 warps x 32 rows f32
#define SMEM_BYTES (OFF_RED + 8 * 32 * 4 + 16)

static __device__ __forceinline__ uint32_t s2u(const void* p) {
    return (uint32_t)__cvta_generic_to_shared(p);
}
static __device__ __forceinline__ uint32_t packbf2(__nv_bfloat16 lo, __nv_bfloat16 hi) {
    __nv_bfloat162 t(lo, hi);
    return *reinterpret_cast<uint32_t*>(&t);
}
static __device__ __forceinline__ void bsplit(float v, __nv_bfloat16& h, __nv_bfloat16& l) {
    h = __float2bfloat16(v);
    l = __float2bfloat16(v - __bfloat162float(h));
}
static __device__ __forceinline__ void mma16816(float* d, const uint32_t* a,
                                                uint32_t b0, uint32_t b1) {
    asm("mma.sync.aligned.m16n8k16.row.col.f32.bf16.bf16.f32 "
        "{%0,%1,%2,%3}, {%4,%5,%6,%7}, {%8,%9}, {%0,%1,%2,%3};"
        : "+f"(d[0]), "+f"(d[1]), "+f"(d[2]), "+f"(d[3])
        : "r"(a[0]), "r"(a[1]), "r"(a[2]), "r"(a[3]), "r"(b0), "r"(b1));
}
static __device__ __forceinline__ void cpa16(uint32_t saddr, const void* gptr) {
    asm volatile("cp.async.cg.shared.global [%0], [%1], 16;"
                 :: "r"(saddr), "l"(__cvta_generic_to_global(gptr)) : "memory");
}

// ---- Prep: convert coeff once into swizzled bf16 hi/lo global tiles ----
__global__ void prep_kernel(const float* __restrict__ coeff) {
    int i = blockIdx.x * blockDim.x + threadIdx.x;
    if (i < 4096 * 7) {
        float v = coeff[i];
        int r = i / 7, j = i - r * 7;
        int n = (r >> 6) * 7 + j;
        int k = r & 63;
        __nv_bfloat16 vh, vl;
        bsplit(v, vh, vl);
        uint32_t cb = (uint32_t)(k * 2) ^ (uint32_t)((n & 7) << 4);
        *reinterpret_cast<__nv_bfloat16*>(g_bh + n * 128 + cb) = vh;
        *reinterpret_cast<__nv_bfloat16*>(g_bl + n * 128 + cb) = vl;
    }
}

__global__ void __launch_bounds__(NTHREADS, 1) anfis_hmma_kernel(
    const float* __restrict__ x, const float* __restrict__ a,
    const float* __restrict__ b, const float* __restrict__ c,
    float* __restrict__ out)
{
    extern __shared__ char smem[];
    const int tid  = threadIdx.x;
    const int lane = tid & 31;
    const int wid  = tid >> 5;
    const int b0   = blockIdx.x * MTILE;

    // ---- Kick off B tile copies (cp.async, overlapped with memberships) ----
    {
        const uint32_t sbh = s2u(smem + OFF_BH);
        const uint32_t sbl = s2u(smem + OFF_BL);
        #pragma unroll
        for (int it = 0; it < B_BYTES / (NTHREADS * 16); it++) {   // 14
            const uint32_t o = (uint32_t)(it * NTHREADS + tid) * 16;
            cpa16(sbh + o, g_bh + o);
            cpa16(sbl + o, g_bl + o);
        }
        asm volatile("cp.async.commit_group;" ::: "memory");
    }

    // ---- Memberships: warp 0 -> P/xp/rden tables, warp 1 -> A (Q) tiles ----
    if (wid < 2) {
        const int bl = lane;
        const int bb = b0 + bl;
        float xi[6], mm[6][4];
        float den = 1.0f;
        #pragma unroll
        for (int i = 0; i < 6; i++) {
            xi[i] = __ldg(&x[bb * 6 + i]);
            float s = 0.0f;
            #pragma unroll
            for (int k = 0; k < 4; k++) {
                float av = __ldg(&a[i * 4 + k]);
                float bv = __ldg(&b[i * 4 + k]);
                float cv = __ldg(&c[i * 4 + k]);
                float d  = (xi[i] - cv) / av;
                float d2 = d * d;
                float db = (bv == 2.0f) ? (d2 * d2) : __powf(d2, bv);
                float mv = 1.0f / (1.0f + db);
                mm[i][k] = mv;
                s += mv;
            }
            den *= s;
        }
        if (wid == 0) {
            float* Ps = reinterpret_cast<float*>(smem + OFF_P);
            float* Xs = reinterpret_cast<float*>(smem + OFF_XP);
            float* Rd = reinterpret_cast<float*>(smem + OFF_RD);
            #pragma unroll
            for (int j = 0; j < 6; j++) Xs[j * 33 + bl] = xi[j];
            Xs[6 * 33 + bl] = 1.0f;
            Rd[bl] = 1.0f / fmaxf(den, 1e-12f);
            float m01[16];
            #pragma unroll
            for (int u = 0; u < 4; u++)
                #pragma unroll
                for (int v = 0; v < 4; v++) m01[u * 4 + v] = mm[0][u] * mm[1][v];
            #pragma unroll
            for (int h = 0; h < 64; h++)
                Ps[h * 33 + bl] = m01[h >> 2] * mm[2][h & 3];
        } else {
            float m34[16];
            #pragma unroll
            for (int u = 0; u < 4; u++)
                #pragma unroll
                for (int v = 0; v < 4; v++) m34[u * 4 + v] = mm[3][u] * mm[4][v];
            #pragma unroll
            for (int l = 0; l < 64; l += 2) {
                float q0 = m34[l >> 2] * mm[5][l & 3];
                float q1 = m34[(l + 1) >> 2] * mm[5][(l + 1) & 3];
                __nv_bfloat16 h0, l0, h1, l1;
                bsplit(q0, h0, l0);
                bsplit(q1, h1, l1);
                uint32_t cb = (uint32_t)(l * 2) ^ (uint32_t)((bl & 7) << 4);
                *reinterpret_cast<uint32_t*>(smem + OFF_AH + bl * 128 + cb) = packbf2(h0, h1);
                *reinterpret_cast<uint32_t*>(smem + OFF_AL + bl * 128 + cb) = packbf2(l0, l1);
            }
        }
    }
    asm volatile("cp.async.wait_group 0;" ::: "memory");
    __syncthreads();

    // ---- HMMA mainloop: warp = 56-col chunk; 2 mtiles x 7 ntiles x 3 terms ----
    float acc[2][7][4];
    #pragma unroll
    for (int mt = 0; mt < 2; mt++)
        #pragma unroll
        for (int nt = 0; nt < 7; nt++)
            #pragma unroll
            for (int e = 0; e < 4; e++) acc[mt][nt][e] = 0.0f;

    const int r  = lane >> 2;
    const int c4 = (lane & 3) * 4;
    const uint32_t rsw = (uint32_t)(r << 4);

    #pragma unroll
    for (int ks = 0; ks < 4; ks++) {
        const uint32_t cb0 = (uint32_t)(ks * 32 + c4) ^ rsw;
        const uint32_t cb1 = (uint32_t)(ks * 32 + c4 + 16) ^ rsw;
        uint32_t ah[2][4], al[2][4];
        #pragma unroll
        for (int mt = 0; mt < 2; mt++) {
            const int row = mt * 16 + r;
            ah[mt][0] = *reinterpret_cast<const uint32_t*>(smem + OFF_AH + row * 128 + cb0);
            ah[mt][1] = *reinterpret_cast<const uint32_t*>(smem + OFF_AH + (row + 8) * 128 + cb0);
            ah[mt][2] = *reinterpret_cast<const uint32_t*>(smem + OFF_AH + row * 128 + cb1);
            ah[mt][3] = *reinterpret_cast<const uint32_t*>(smem + OFF_AH + (row + 8) * 128 + cb1);
            al[mt][0] = *reinterpret_cast<const uint32_t*>(smem + OFF_AL + row * 128 + cb0);
            al[mt][1] = *reinterpret_cast<const uint32_t*>(smem + OFF_AL + (row + 8) * 128 + cb0);
            al[mt][2] = *reinterpret_cast<const uint32_t*>(smem + OFF_AL + row * 128 + cb1);
            al[mt][3] = *reinterpret_cast<const uint32_t*>(smem + OFF_AL + (row + 8) * 128 + cb1);
        }
        #pragma unroll
        for (int nt = 0; nt < 7; nt++) {
            const int n = wid * 56 + nt * 8 + r;      // n & 7 == r
            uint32_t bh0 = *reinterpret_cast<const uint32_t*>(smem + OFF_BH + n * 128 + cb0);
            uint32_t bh1 = *reinterpret_cast<const uint32_t*>(smem + OFF_BH + n * 128 + cb1);
            uint32_t bl0 = *reinterpret_cast<const uint32_t*>(smem + OFF_BL + n * 128 + cb0);
            uint32_t bl1 = *reinterpret_cast<const uint32_t*>(smem + OFF_BL + n * 128 + cb1);
            #pragma unroll
            for (int mt = 0; mt < 2; mt++) {
                mma16816(acc[mt][nt], ah[mt], bh0, bh1);   // hi*hi
                mma16816(acc[mt][nt], ah[mt], bl0, bl1);   // hi*lo
                mma16816(acc[mt][nt], al[mt], bh0, bh1);   // lo*hi
            }
        }
    }

    // ---- Epilogue: fold P * x_plus into fragments, reduce to rows ----
    {
        const float* Ps = reinterpret_cast<const float*>(smem + OFF_P);
        const float* Xs = reinterpret_cast<const float*>(smem + OFF_XP);
        float rsum[4] = {0.f, 0.f, 0.f, 0.f};
        #pragma unroll
        for (int mt = 0; mt < 2; mt++)
            #pragma unroll
            for (int nt = 0; nt < 7; nt++)
                #pragma unroll
                for (int e = 0; e < 4; e++) {
                    const int row = mt * 16 + r + (e >> 1) * 8;
                    const int u   = nt * 8 + 2 * (lane & 3) + (e & 1);
                    const int h   = u / 7;
                    const int j   = u - h * 7;
                    float pv = Ps[(wid * 8 + h) * 33 + row];
                    float xv = Xs[j * 33 + row];
                    rsum[mt * 2 + (e >> 1)] =
                        fmaf(pv * xv, acc[mt][nt][e], rsum[mt * 2 + (e >> 1)]);
                }
        #pragma unroll
        for (int i = 0; i < 4; i++) {
            rsum[i] += __shfl_xor_sync(0xFFFFFFFFu, rsum[i], 1);
            rsum[i] += __shfl_xor_sync(0xFFFFFFFFu, rsum[i], 2);
        }
        if ((lane & 3) == 0) {
            float* red = reinterpret_cast<float*>(smem + OFF_RED);
            #pragma unroll
            for (int i = 0; i < 4; i++)
                red[wid * 32 + r + 8 * i] = rsum[i];
        }
    }
    __syncthreads();

    // ---- Final: sum 8 warp chunks, normalize, store ----
    if (tid < MTILE) {
        const float* red = reinterpret_cast<const float*>(smem + OFF_RED);
        const float* Rd  = reinterpret_cast<const float*>(smem + OFF_RD);
        float num = 0.0f;
        #pragma unroll
        for (int w = 0; w < 8; w++) num += red[w * 32 + tid];
        out[b0 + tid] = num * Rd[tid];
    }
}

extern "C" void kernel_launch(void* const* d_in, const int* in_sizes, int n_in,
                              void* d_out, int out_size) {
    const float* x     = (const float*)d_in[0];
    const float* a     = (const float*)d_in[1];
    const float* b     = (const float*)d_in[2];
    const float* c     = (const float*)d_in[3];
    const float* coeff = (const float*)d_in[4];
    // d_in[5] = mf_indices: full itertools.product enumeration; base-4 digit
    // decode is analytic, index tensor unused.
    float* out = (float*)d_out;

    static bool attr_set = false;
    if (!attr_set) {
        cudaFuncSetAttribute(anfis_hmma_kernel,
                             cudaFuncAttributeMaxDynamicSharedMemorySize, SMEM_BYTES);
        attr_set = true;
    }
    prep_kernel<<<(4096 * 7 + 255) / 256, 256>>>(coeff);
    anfis_hmma_kernel<<<NBLOCKS, NTHREADS, SMEM_BYTES>>>(x, a, b, c, out);
}